// round 7
// baseline (speedup 1.0000x reference)
#include <cuda_runtime.h>
#include <cuda_bf16.h>

// TrajectoryScore: segmented streaming reduction, single fused kernel.
// 64 segments x 100k obs; 24B read per obs -> 153.6MB. Memory-bound.
//
// - Direct 48B-stride float4 loads (3+3 LDG.128 per 4 obs, 100% sector
//   utilization), mixture-model math w/ fast intrinsics.
// - BPS=16 -> 1024 blocks: single wave, per-SM block counts {6,7}
//   (straggler 1.01x vs 1.16x at 512 blocks).
// - Block reduce -> per-block partials; last arriving block (threadfence +
//   atomic counter) sums partials in fixed order, writes 3*B outputs.
//   Counter self-resets -> graph-replay deterministic, no allocations.

#define BPS   16     // blocks per segment
#define NTHR  256    // threads per block
#define NWPB  (NTHR / 32)
#define MAX_B 256

__device__ float    g_partial[MAX_B * BPS * 2];
__device__ unsigned g_count = 0;

__global__ __launch_bounds__(NTHR)
void score_kernel(const float* __restrict__ u_pred,
                  const float* __restrict__ u_obs,
                  const float* __restrict__ h_arr,
                  const float* __restrict__ lam_arr,
                  const float* __restrict__ thr_arr,
                  float* __restrict__ out,
                  int n_per)
{
    const int seg  = blockIdx.y;
    const int wid  = threadIdx.x >> 5;
    const int lane = threadIdx.x & 31;

    // Per-segment constants (uniform across block)
    const float T     = thr_arr[seg];
    const float hh    = h_arr[seg];
    const float lm    = lam_arr[seg];
    const float q     = 1.0f - hh;
    const float c     = hh * lm / (1.0f - __expf(-lm));
    const float scale = -lm / T;   // exp(-lam * s2/T)

    float accL = 0.0f;   // sum log(p) over close obs
    float accH = 0.0f;   // sum p_hit_post over close & real-hit obs

#define DO_OBS(dx, dy, dz)                                              \
    {                                                                   \
        float s2 = (dx) * (dx);                                         \
        s2 = fmaf((dy), (dy), s2);                                      \
        s2 = fmaf((dz), (dz), s2);                                      \
        float e    = __expf(s2 * scale);                                \
        float ph   = c * e;                                             \
        float p    = ph + q;                                            \
        float lp   = __logf(p);                                         \
        float post = __fdividef(ph, p);                                 \
        bool close = s2 < T;                                            \
        accL += close ? lp : 0.0f;                                      \
        accH += (close && post > 0.95f) ? post : 0.0f;                  \
    }

    const long long segf = (long long)seg * (long long)n_per * 3LL;
    const int ngrp = n_per >> 2;   // groups of 4 obs (= 3 float4s per array)

    if ((((long long)n_per * 3LL) & 3LL) == 0) {
        const float4* __restrict__ pred4 = (const float4*)u_pred + (segf >> 2);
        const float4* __restrict__ obs4  = (const float4*)u_obs  + (segf >> 2);
        for (int g = blockIdx.x * NTHR + threadIdx.x; g < ngrp;
             g += BPS * NTHR) {
            const int b = 3 * g;
            float4 p0 = pred4[b + 0];
            float4 p1 = pred4[b + 1];
            float4 p2 = pred4[b + 2];
            float4 o0 = obs4[b + 0];
            float4 o1 = obs4[b + 1];
            float4 o2 = obs4[b + 2];
            DO_OBS(p0.x - o0.x, p0.y - o0.y, p0.z - o0.z);
            DO_OBS(p0.w - o0.w, p1.x - o1.x, p1.y - o1.y);
            DO_OBS(p1.z - o1.z, p1.w - o1.w, p2.x - o2.x);
            DO_OBS(p2.y - o2.y, p2.z - o2.z, p2.w - o2.w);
        }
        // tail obs (n_per % 4), scalar, chunk 0 only
        if (blockIdx.x == 0) {
            for (int i = ngrp * 4 + threadIdx.x; i < n_per; i += NTHR) {
                const float* pp = u_pred + segf + 3LL * i;
                const float* oo = u_obs  + segf + 3LL * i;
                DO_OBS(pp[0] - oo[0], pp[1] - oo[1], pp[2] - oo[2]);
            }
        }
    } else {
        // generic scalar fallback (not hit for this shape)
        for (int i = blockIdx.x * NTHR + threadIdx.x; i < n_per;
             i += BPS * NTHR) {
            const float* pp = u_pred + segf + 3LL * i;
            const float* oo = u_obs  + segf + 3LL * i;
            DO_OBS(pp[0] - oo[0], pp[1] - oo[1], pp[2] - oo[2]);
        }
    }
#undef DO_OBS

    // -------- block reduction --------
    #pragma unroll
    for (int o = 16; o > 0; o >>= 1) {
        accL += __shfl_down_sync(0xffffffffu, accL, o);
        accH += __shfl_down_sync(0xffffffffu, accH, o);
    }

    __shared__ float sL[NWPB];
    __shared__ float sH[NWPB];
    if (lane == 0) { sL[wid] = accL; sH[wid] = accH; }
    __syncthreads();

    if (wid == 0) {
        accL = (lane < NWPB) ? sL[lane] : 0.0f;
        accH = (lane < NWPB) ? sH[lane] : 0.0f;
        #pragma unroll
        for (int o = NWPB / 2; o > 0; o >>= 1) {
            accL += __shfl_down_sync(0xffffffffu, accL, o);
            accH += __shfl_down_sync(0xffffffffu, accH, o);
        }
        if (lane == 0) {
            const int idx = (seg * BPS + blockIdx.x) * 2;
            g_partial[idx + 0] = accL;
            g_partial[idx + 1] = accH;
        }
    }

    // -------- last-block final reduction (deterministic fixed order) -----
    __shared__ bool isLast;
    if (threadIdx.x == 0) {
        __threadfence();
        unsigned v = atomicAdd(&g_count, 1u);
        isLast = (v == gridDim.x * gridDim.y - 1);
    }
    __syncthreads();

    if (isLast) {
        __threadfence();
        const int B = gridDim.y;
        for (int j = threadIdx.x; j < B; j += NTHR) {
            float fL = 0.0f, fH = 0.0f;
            #pragma unroll
            for (int b = 0; b < BPS; b++) {
                fL += g_partial[(j * BPS + b) * 2 + 0];
                fH += g_partial[(j * BPS + b) * 2 + 1];
            }
            out[j]         = fL;   // log_like
            out[B + j]     = fH;   // hits
            out[2 * B + j] = fH;   // hits_raw
        }
        if (threadIdx.x == 0) g_count = 0;   // reset for next graph replay
    }
}

extern "C" void kernel_launch(void* const* d_in, const int* in_sizes, int n_in,
                              void* d_out, int out_size)
{
    const float* u_pred = (const float*)d_in[0];
    const float* u_obs  = (const float*)d_in[1];
    const float* h      = (const float*)d_in[2];
    const float* lam    = (const float*)d_in[3];
    const float* thr    = (const float*)d_in[4];
    float* out = (float*)d_out;

    const int B = out_size / 3;
    long long e0 = in_sizes[0];
    long long N = (e0 % 3 == 0) ? (e0 / 3) : e0;
    const int n_per = (int)(N / B);

    dim3 grid(BPS, B);
    score_kernel<<<grid, NTHR>>>(u_pred, u_obs, h, lam, thr, out, n_per);
}

// round 8
// speedup vs baseline: 1.0534x; 1.0534x over previous
#include <cuda_runtime.h>
#include <cuda_bf16.h>

// TrajectoryScore: segmented streaming reduction, single fused kernel.
// 64 segments x 100k obs, 24B/obs -> 153.6MB streamed. Memory-bound.
//
// Flat perfectly-balanced grid: 456 = 152 SMs x 3 blocks, each block takes an
// equal contiguous chunk of 4-obs groups (chunk spans <= 2 segments).
// Per-group segment constants selected by predicate (no divergence, no float
// atomics). Direct 48B-stride float4 loads (100% sector utilization).
// Last arriving block sums per-block partials in fixed order -> deterministic.

#define NTHR  256
#define NWPB  (NTHR / 32)
#define GRID  456              // 152 SMs * 3 CTAs: one balanced wave
#define BPS   8                // fallback kernel: blocks per segment
#define MAX_B 256

__device__ float    g_partial[4 * GRID > 2 * MAX_B * BPS ? 4 * GRID : 2 * MAX_B * BPS];
__device__ unsigned g_count = 0;

// observation scoring: returns contributions via accL/accH
#define DO_OBS(dx, dy, dz, T, q, c, k, accL, accH)                      \
    {                                                                   \
        float s2 = (dx) * (dx);                                         \
        s2 = fmaf((dy), (dy), s2);                                      \
        s2 = fmaf((dz), (dz), s2);                                      \
        float e    = __expf(s2 * (k));                                  \
        float ph   = (c) * e;                                           \
        float p    = ph + (q);                                          \
        float lp   = __logf(p);                                         \
        float post = __fdividef(ph, p);                                 \
        bool close = s2 < (T);                                          \
        accL += close ? lp : 0.0f;                                      \
        accH += (close && post > 0.95f) ? post : 0.0f;                  \
    }

__device__ __forceinline__ void load_consts(const float* h_arr,
                                            const float* lam_arr,
                                            const float* thr_arr, int s,
                                            float& T, float& q, float& c,
                                            float& k)
{
    T = thr_arr[s];
    float hh = h_arr[s];
    float lm = lam_arr[s];
    q = 1.0f - hh;
    c = hh * lm / (1.0f - __expf(-lm));
    k = -lm / T;
}

// ---------------------------------------------------------------------------
// Flat kernel: requires n_per % 4 == 0 and 4*GC <= n_per (<=2 segs per block)
// ---------------------------------------------------------------------------
__global__ __launch_bounds__(NTHR)
void score_flat(const float* __restrict__ u_pred,
                const float* __restrict__ u_obs,
                const float* __restrict__ h_arr,
                const float* __restrict__ lam_arr,
                const float* __restrict__ thr_arr,
                float* __restrict__ out,
                int n_per, int B, int GC, int G4, long long Nobs)
{
    const int b    = blockIdx.x;
    const int gper = n_per >> 2;            // groups per segment
    const int gbeg = b * GC;
    const int gend = min(gbeg + GC, G4);

    int seg0 = gbeg / gper;                 // one divide per block
    if (seg0 >= B) seg0 = B - 1;            // empty trailing blocks
    const int seg1   = min(seg0 + 1, B - 1);
    const int gbound = (seg0 + 1) * gper;   // groups >= gbound are in seg1

    float T0, q0, c0, k0, T1, q1, c1, k1;
    load_consts(h_arr, lam_arr, thr_arr, seg0, T0, q0, c0, k0);
    load_consts(h_arr, lam_arr, thr_arr, seg1, T1, q1, c1, k1);

    float L0 = 0.f, H0 = 0.f, L1 = 0.f, H1 = 0.f;

    const float4* __restrict__ p4 = (const float4*)u_pred;
    const float4* __restrict__ o4 = (const float4*)u_obs;

    for (int g = gbeg + threadIdx.x; g < gend; g += NTHR) {
        const int base = 3 * g;
        float4 a0 = p4[base + 0];
        float4 a1 = p4[base + 1];
        float4 a2 = p4[base + 2];
        float4 b0 = o4[base + 0];
        float4 b1 = o4[base + 1];
        float4 b2 = o4[base + 2];

        const bool s = (g >= gbound);
        const float T = s ? T1 : T0;
        const float q = s ? q1 : q0;
        const float c = s ? c1 : c0;
        const float k = s ? k1 : k0;

        float tL = 0.f, tH = 0.f;
        DO_OBS(a0.x - b0.x, a0.y - b0.y, a0.z - b0.z, T, q, c, k, tL, tH);
        DO_OBS(a0.w - b0.w, a1.x - b1.x, a1.y - b1.y, T, q, c, k, tL, tH);
        DO_OBS(a1.z - b1.z, a1.w - b1.w, a2.x - b2.x, T, q, c, k, tL, tH);
        DO_OBS(a2.y - b2.y, a2.z - b2.z, a2.w - b2.w, T, q, c, k, tL, tH);

        L0 += s ? 0.f : tL;
        L1 += s ? tL : 0.f;
        H0 += s ? 0.f : tH;
        H1 += s ? tH : 0.f;
    }

    // ---- block reduction of 4 values ----
    #pragma unroll
    for (int o = 16; o > 0; o >>= 1) {
        L0 += __shfl_down_sync(0xffffffffu, L0, o);
        H0 += __shfl_down_sync(0xffffffffu, H0, o);
        L1 += __shfl_down_sync(0xffffffffu, L1, o);
        H1 += __shfl_down_sync(0xffffffffu, H1, o);
    }
    __shared__ float sV[4][NWPB];
    const int wid  = threadIdx.x >> 5;
    const int lane = threadIdx.x & 31;
    if (lane == 0) { sV[0][wid] = L0; sV[1][wid] = H0; sV[2][wid] = L1; sV[3][wid] = H1; }
    __syncthreads();
    if (wid == 0) {
        L0 = (lane < NWPB) ? sV[0][lane] : 0.f;
        H0 = (lane < NWPB) ? sV[1][lane] : 0.f;
        L1 = (lane < NWPB) ? sV[2][lane] : 0.f;
        H1 = (lane < NWPB) ? sV[3][lane] : 0.f;
        #pragma unroll
        for (int o = NWPB / 2; o > 0; o >>= 1) {
            L0 += __shfl_down_sync(0xffffffffu, L0, o);
            H0 += __shfl_down_sync(0xffffffffu, H0, o);
            L1 += __shfl_down_sync(0xffffffffu, L1, o);
            H1 += __shfl_down_sync(0xffffffffu, H1, o);
        }
        if (lane == 0) {
            g_partial[b * 4 + 0] = L0;
            g_partial[b * 4 + 1] = H0;
            g_partial[b * 4 + 2] = L1;
            g_partial[b * 4 + 3] = H1;
        }
    }

    // ---- last-block final reduction (fixed order, deterministic) ----
    __shared__ bool isLast;
    if (threadIdx.x == 0) {
        __threadfence();
        unsigned v = atomicAdd(&g_count, 1u);
        isLast = (v == gridDim.x - 1);
    }
    __syncthreads();

    if (isLast) {
        __threadfence();
        const int j = threadIdx.x;
        if (j < B) {
            const int jg     = j * gper;
            const int bstart = jg / GC;
            const int bend   = ((j + 1) * gper - 1) / GC;
            float fL = 0.f, fH = 0.f;
            for (int bb = bstart; bb <= bend; bb++) {
                // only bstart can be this segment's "second" (slot1) segment
                const int slot = (bb == bstart && bb * GC < jg) ? 1 : 0;
                fL += g_partial[bb * 4 + slot * 2 + 0];
                fH += g_partial[bb * 4 + slot * 2 + 1];
            }
            // tail obs (Nobs % 4): scalar, tiny
            for (long long i = 4LL * G4; i < Nobs; i++) {
                if ((int)(i / n_per) == j) {
                    const float* pp = u_pred + 3 * i;
                    const float* oo = u_obs  + 3 * i;
                    float T, q, c, k;
                    load_consts(h_arr, lam_arr, thr_arr, j, T, q, c, k);
                    DO_OBS(pp[0] - oo[0], pp[1] - oo[1], pp[2] - oo[2],
                           T, q, c, k, fL, fH);
                }
            }
            out[j]         = fL;
            out[B + j]     = fH;
            out[2 * B + j] = fH;
        }
        if (threadIdx.x == 0) g_count = 0;   // reset for next graph replay
    }
}

// ---------------------------------------------------------------------------
// Fallback: per-segment grid, scalar loads (any shape)
// ---------------------------------------------------------------------------
__global__ __launch_bounds__(NTHR)
void score_fallback(const float* __restrict__ u_pred,
                    const float* __restrict__ u_obs,
                    const float* __restrict__ h_arr,
                    const float* __restrict__ lam_arr,
                    const float* __restrict__ thr_arr,
                    float* __restrict__ out,
                    int n_per)
{
    const int seg  = blockIdx.y;
    const int wid  = threadIdx.x >> 5;
    const int lane = threadIdx.x & 31;

    float T, q, c, k;
    load_consts(h_arr, lam_arr, thr_arr, seg, T, q, c, k);

    float accL = 0.f, accH = 0.f;
    const long long segf = (long long)seg * (long long)n_per * 3LL;
    for (int i = blockIdx.x * NTHR + threadIdx.x; i < n_per; i += BPS * NTHR) {
        const float* pp = u_pred + segf + 3LL * i;
        const float* oo = u_obs  + segf + 3LL * i;
        DO_OBS(pp[0] - oo[0], pp[1] - oo[1], pp[2] - oo[2], T, q, c, k,
               accL, accH);
    }

    #pragma unroll
    for (int o = 16; o > 0; o >>= 1) {
        accL += __shfl_down_sync(0xffffffffu, accL, o);
        accH += __shfl_down_sync(0xffffffffu, accH, o);
    }
    __shared__ float sL[NWPB], sH[NWPB];
    if (lane == 0) { sL[wid] = accL; sH[wid] = accH; }
    __syncthreads();
    if (wid == 0) {
        accL = (lane < NWPB) ? sL[lane] : 0.f;
        accH = (lane < NWPB) ? sH[lane] : 0.f;
        #pragma unroll
        for (int o = NWPB / 2; o > 0; o >>= 1) {
            accL += __shfl_down_sync(0xffffffffu, accL, o);
            accH += __shfl_down_sync(0xffffffffu, accH, o);
        }
        if (lane == 0) {
            g_partial[(seg * BPS + blockIdx.x) * 2 + 0] = accL;
            g_partial[(seg * BPS + blockIdx.x) * 2 + 1] = accH;
        }
    }

    __shared__ bool isLast;
    if (threadIdx.x == 0) {
        __threadfence();
        unsigned v = atomicAdd(&g_count, 1u);
        isLast = (v == gridDim.x * gridDim.y - 1);
    }
    __syncthreads();
    if (isLast) {
        __threadfence();
        const int B = gridDim.y;
        for (int j = threadIdx.x; j < B; j += NTHR) {
            float fL = 0.f, fH = 0.f;
            #pragma unroll
            for (int bb = 0; bb < BPS; bb++) {
                fL += g_partial[(j * BPS + bb) * 2 + 0];
                fH += g_partial[(j * BPS + bb) * 2 + 1];
            }
            out[j]         = fL;
            out[B + j]     = fH;
            out[2 * B + j] = fH;
        }
        if (threadIdx.x == 0) g_count = 0;
    }
}

extern "C" void kernel_launch(void* const* d_in, const int* in_sizes, int n_in,
                              void* d_out, int out_size)
{
    const float* u_pred = (const float*)d_in[0];
    const float* u_obs  = (const float*)d_in[1];
    const float* h      = (const float*)d_in[2];
    const float* lam    = (const float*)d_in[3];
    const float* thr    = (const float*)d_in[4];
    float* out = (float*)d_out;

    const int B = out_size / 3;
    long long e0 = in_sizes[0];
    long long N = (e0 % 3 == 0) ? (e0 / 3) : e0;
    const int n_per = (int)(N / B);

    if ((n_per & 3) == 0) {
        const int G4 = (int)(N >> 2);                // total 4-obs groups
        const int GC = (G4 + GRID - 1) / GRID;       // groups per block
        if (4 * GC <= n_per) {                       // <=2 segments per block
            score_flat<<<GRID, NTHR>>>(u_pred, u_obs, h, lam, thr, out,
                                       n_per, B, GC, G4, N);
            return;
        }
    }
    dim3 grid(BPS, B);
    score_fallback<<<grid, NTHR>>>(u_pred, u_obs, h, lam, thr, out, n_per);
}